// round 15
// baseline (speedup 1.0000x reference)
#include <cuda_runtime.h>
#include <math.h>
#include <limits.h>

#define NMESH  256
#define MSTEPS 4096
#define SLEN   (MSTEPS + 1)     // scan steps 0..M (step 0 = pseudo init sweep-up at hc=1.0)
#define SLENP  4128             // padded to multiple of 32 (129 chunks)
#define NCH    (SLENP / 32)     // 129
#define NCHP   136
#define LOGC   8                // sparse-table levels over chunk arrays (2^7=128 >= NCH/2)
#define TRI    (NMESH * (NMESH + 1) / 2)
#define SENTD  32767
#define CHUNK  8
#define ILPAD  4112             // SLEN padded to multiple of 4 for uint4 copy
#define NWORK  32               // working blocks
#define NGRID  148
#define NSUB   9                // density sub-barrier participants (blocks 0-8)
#define TPB    1024

// ---------------- device scratch ----------------
__device__ float  g_P[TRI];                   // per-row inclusive prefix of softplus density
__device__ float  g_rowsum[NMESH];
__device__ int    g_il[ILPAD];                // packed: (iu:9)<<22 | (link+1:13)<<9 | (segMin+1:9)
__device__ int    g_start[SLEN];              // packed: lastup<<9 | (dminLast+1)
__device__ float  g_A[NMESH + 1];             // prefix of rowsums; g_A[NMESH] = S
__device__ float  g_colpreT[NMESH * NMESH];   // colpreT[k*N+j] = sum_{r=j..k} P_r(j)

// barriers (generation-based; persist across graph replays)
__device__ volatile int g_bar_count = 0, g_bar_gen = 0;   // full (NWORK blocks)
__device__ volatile int g_sub_count = 0, g_sub_gen = 0;   // density group (NSUB blocks)

__device__ __forceinline__ void barrier_n(volatile int* cnt, volatile int* gen, int target) {
    __syncthreads();
    if (threadIdx.x == 0) {
        int g = *gen;
        __threadfence();
        if (atomicAdd((int*)cnt, 1) == target - 1) {
            *cnt = 0;
            __threadfence();
            *gen = g + 1;
        } else {
            while (*gen == g) { }
        }
        __threadfence();
    }
    __syncthreads();
}

__device__ __forceinline__ float softplusf(float x) {
    return fmaxf(x, 0.f) + log1pf(expf(-fabsf(x)));
}

// shared-memory overlay
union SMem {
    struct {   // meta pipeline, blocks 16-31 (redundant metaA + local partB)
        float lin[NMESH];
        short s_iu[SLENP];
        short s_d[SLENP];
        short s_lu[SLENP];
        short pmind[SLENP];
        short smind[SLENP];
        short cmind[NCHP];
        short cmaxu[NCHP];
        short stu[LOGC * NCHP];    // sparse max over cmaxu
        short stdm[LOGC * NCHP];   // sparse min over cmind
        int   sc[32];
    } meta;
    struct {   // colpre tile, blocks 0-7
        float tile[NMESH * 33];
    } cp;
    struct {   // phase 3, all working blocks
        int   s_il[ILPAD];
        float s_A[NMESH + 1];
    } walk;
};

__global__ void __launch_bounds__(TPB, 1) k_fused(const float* __restrict__ h,
                                                  const float* __restrict__ raw,
                                                  const float* __restrict__ m2,
                                                  const float* __restrict__ m3,
                                                  float* __restrict__ out) {
    int b = blockIdx.x;
    if (b >= NWORK) return;

    __shared__ SMem sm;
    int tid = threadIdx.x;
    int lane = tid & 31, w = tid >> 5;

    if (b >= 16) {
        // ============ meta pipeline (blocks 16-31, fully local) ============
        if (tid < NMESH) {
            const float* xx = (m2[1] != m2[0]) ? m2 : m3;
            sm.meta.lin[tid] = xx[tid];
        }
        __syncthreads();

        // ---- classification: arithmetic candidate + exact fixup on mesh floats ----
        for (int s = tid; s < SLENP; s += TPB) {
            short iu = 0, dd = (short)SENTD;
            if (s < SLEN) {
                float hc, hp;
                if (s == 0) { hc = 1.0f; hp = h[MSTEPS - 1]; }
                else { hc = h[s - 1]; hp = (s == 1) ? 1.0f : h[s - 2]; }
                if (hc > hp) {
                    int m = (int)((hc + 1.0f) * 127.5f);
                    m = min(max(m, 0), 255);
                    while (m > 0 && sm.meta.lin[m - 1] >= hc) m--;
                    while (m < 256 && sm.meta.lin[m] < hc) m++;
                    iu = (short)m;
                } else if (hc < hp) {
                    int m = (int)((hc + 1.0f) * 127.5f);
                    m = min(max(m, 0), 255);
                    while (m > 0 && sm.meta.lin[m - 1] > hc) m--;
                    while (m < 256 && sm.meta.lin[m] <= hc) m++;
                    dd = (short)(m - 1);
                }
            }
            sm.meta.s_iu[s] = iu; sm.meta.s_d[s] = dd;
        }
        __syncthreads();

        // ---- lastup local + chunk mins fused ----
        int v_lu;
        int l0, l1, l2, l3;
        {
            int base = tid * 4;
            int w0 = (sm.meta.s_iu[base]     > 0) ? base     : -1;
            int w1 = (sm.meta.s_iu[base + 1] > 0) ? base + 1 : -1;
            int w2 = (sm.meta.s_iu[base + 2] > 0) ? base + 2 : -1;
            int w3 = (sm.meta.s_iu[base + 3] > 0) ? base + 3 : -1;
            l0 = w0; l1 = max(l0, w1); l2 = max(l1, w2); l3 = max(l2, w3);
            v_lu = l3;
#pragma unroll
            for (int o = 1; o < 32; o <<= 1) { int u = __shfl_up_sync(0xffffffffu, v_lu, o); if (lane >= o) v_lu = max(v_lu, u); }
            if (lane == 31) sm.meta.sc[w] = v_lu;
        }
        // chunk mins
        for (int c = w; c < NCH; c += 32) {
            int e = c * 32 + lane;
            int dv = sm.meta.s_d[e];
            int uv = sm.meta.s_iu[e];
            int p = dv;
#pragma unroll
            for (int o = 1; o < 32; o <<= 1) { int u = __shfl_up_sync(0xffffffffu, p, o); if (lane >= o) p = min(p, u); }
            sm.meta.pmind[e] = (short)p;
            int q = dv;
#pragma unroll
            for (int o = 1; o < 32; o <<= 1) { int u = __shfl_down_sync(0xffffffffu, q, o); if (lane + o < 32) q = min(q, u); }
            sm.meta.smind[e] = (short)q;
            if (lane == 31) sm.meta.cmind[c] = (short)p;
            int m = uv;
#pragma unroll
            for (int o = 16; o >= 1; o >>= 1) m = max(m, __shfl_xor_sync(0xffffffffu, m, o));
            if (lane == 0) sm.meta.cmaxu[c] = (short)m;
        }
        __syncthreads();
        if (w == 0) {
            int x = sm.meta.sc[lane];
#pragma unroll
            for (int o = 1; o < 32; o <<= 1) { int u = __shfl_up_sync(0xffffffffu, x, o); if (lane >= o) x = max(x, u); }
            sm.meta.sc[lane] = x;
        }
        // level-0 of chunk sparse tables (independent of warp-0 scan above)
        for (int i = tid; i < NCHP; i += TPB) {
            sm.meta.stu[i]  = (i < NCH) ? sm.meta.cmaxu[i] : (short)-1;
            sm.meta.stdm[i] = (i < NCH) ? sm.meta.cmind[i] : (short)SENTD;
        }
        __syncthreads();
        {
            int base = tid * 4;
            int warppre = (w > 0) ? sm.meta.sc[w - 1] : INT_MIN;
            int lanepre = __shfl_up_sync(0xffffffffu, v_lu, 1);
            int pre = (lane == 0) ? warppre : max(warppre, lanepre);
            sm.meta.s_lu[base]     = (short)max(pre, l0);
            sm.meta.s_lu[base + 1] = (short)max(pre, l1);
            sm.meta.s_lu[base + 2] = (short)max(pre, l2);
            sm.meta.s_lu[base + 3] = (short)max(pre, l3);
            if (tid == TPB - 1) {
                int w4 = (sm.meta.s_iu[4096] > 0) ? 4096 : -1;
                sm.meta.s_lu[4096] = (short)max(max(pre, l3), w4);
            }
        }
        // build sparse-table levels 1..LOGC-1 over chunk arrays
        for (int k = 1; k < LOGC; k++) {
            int half = 1 << (k - 1);
            __syncthreads();
            if (tid < NCH) {
                int i = tid;
                short a = sm.meta.stu[(k - 1) * NCHP + i];
                short bb = (i + half < NCH) ? sm.meta.stu[(k - 1) * NCHP + i + half] : (short)-1;
                short c = sm.meta.stdm[(k - 1) * NCHP + i];
                short dd2 = (i + half < NCH) ? sm.meta.stdm[(k - 1) * NCHP + i + half] : (short)SENTD;
                sm.meta.stu[k * NCHP + i]  = a > bb ? a : bb;
                sm.meta.stdm[k * NCHP + i] = c < dd2 ? c : dd2;
            }
        }
        __syncthreads();

        // ---- partB: each block handles 257 s-values; all scans log-bounded ----
        {
            int s = (b - 16) * 257 + tid;
            if (tid < 257 && s < SLEN) {
                int iu = sm.meta.s_iu[s];
                int lnk = -1;
                int e = 257;                              // segMin+1 encoding; 257 = +inf
                if (iu > 0 && iu < NMESH - 1) {
                    // PGE: rightmost s' < s with iu[s'] > iu
                    int ci = (s - 1) >> 5;
                    int base = ci << 5;
                    int found = -1;
#pragma unroll
                    for (int ii = 0; ii < 32; ii++) {
                        int idx = base + ii;
                        int val = sm.meta.s_iu[idx];
                        if (idx < s && val > iu) found = idx;
                    }
                    if (found < 0) {
                        // chunk-level: rightmost chunk c' <= ci-1 with cmaxu > iu
                        // (guaranteed to exist: chunk 0 holds s=0 with iu=255)
                        int L = 0, R = ci - 1;
                        while (L < R) {
                            int mid = (L + R + 1) >> 1;
                            int k2 = 31 - __clz(R - mid + 1);
                            int mx = max((int)sm.meta.stu[k2 * NCHP + mid],
                                         (int)sm.meta.stu[k2 * NCHP + R - (1 << k2) + 1]);
                            if (mx > iu) L = mid; else R = mid - 1;
                        }
                        base = L << 5;
#pragma unroll
                        for (int ii = 0; ii < 32; ii++) {
                            int idx = base + ii;
                            int val = sm.meta.s_iu[idx];
                            if (val > iu) found = idx;
                        }
                    }
                    lnk = found;
                    // segMin d over [lnk+1, s]
                    int l = lnk + 1, r = s;
                    int cl = l >> 5, cr = r >> 5;
                    int v;
                    if (cl == cr) {
                        v = SENTD;
                        int cb = cl << 5;
#pragma unroll
                        for (int ii = 0; ii < 32; ii++) {
                            int idx = cb + ii;
                            int dv = sm.meta.s_d[idx];
                            if (idx >= l && idx <= r) v = min(v, dv);
                        }
                    } else {
                        v = min((int)sm.meta.smind[l], (int)sm.meta.pmind[r]);
                        if (cl + 1 <= cr - 1) {
                            int len = cr - 1 - cl;
                            int k2 = 31 - __clz(len);
                            v = min(v, min((int)sm.meta.stdm[k2 * NCHP + cl + 1],
                                           (int)sm.meta.stdm[k2 * NCHP + cr - (1 << k2)]));
                        }
                    }
                    e = min(v + 1, 257);
                }
                g_il[s] = (iu << 22) | ((lnk + 1) << 9) | e;

                // g_start: lastup + min d over (lastup, s]
                int lu = sm.meta.s_lu[s];
                int enc = 257;
                if (lu < s) {
                    int l = lu + 1, r = s;
                    int cl = l >> 5, cr = r >> 5;
                    int v;
                    if (cl == cr) {
                        v = SENTD;
                        int cb = cl << 5;
#pragma unroll
                        for (int ii = 0; ii < 32; ii++) {
                            int idx = cb + ii;
                            int dv = sm.meta.s_d[idx];
                            if (idx >= l && idx <= r) v = min(v, dv);
                        }
                    } else {
                        v = min((int)sm.meta.smind[l], (int)sm.meta.pmind[r]);
                        if (cl + 1 <= cr - 1) {
                            int len = cr - 1 - cl;
                            int k2 = 31 - __clz(len);
                            v = min(v, min((int)sm.meta.stdm[k2 * NCHP + cl + 1],
                                           (int)sm.meta.stdm[k2 * NCHP + cr - (1 << k2)]));
                        }
                    }
                    enc = min(v + 1, 257);
                }
                g_start[s] = (lu << 9) | enc;
            }
            if (b == 16 && tid >= 512 && tid < 512 + (ILPAD - SLEN)) g_il[SLEN + (tid - 512)] = 0;
        }
    } else if (b < NSUB) {
        // ============ density pipeline (blocks 0-8) ============
        if (b < 8) {
            int r = b * 32 + w;
            int off = r * (r + 1) / 2;
            float v[8];
#pragma unroll
            for (int seg = 0; seg < 8; seg++) {
                int idx = seg * 32 + lane;
                v[seg] = (idx <= r) ? raw[off + idx] : 0.f;
            }
#pragma unroll
            for (int seg = 0; seg < 8; seg++) {
                int idx = seg * 32 + lane;
                v[seg] = (idx <= r) ? softplusf(v[seg]) : 0.f;
            }
            float carry = 0.f;
#pragma unroll
            for (int seg = 0; seg < 8; seg++) {
                if (seg * 32 <= r) {
                    float x = v[seg];
#pragma unroll
                    for (int o = 1; o < 32; o <<= 1) { float u = __shfl_up_sync(0xffffffffu, x, o); if (lane >= o) x += u; }
                    x += carry;
                    int idx = seg * 32 + lane;
                    if (idx <= r) g_P[off + idx] = x;
                    carry = __shfl_sync(0xffffffffu, x, 31);
                }
            }
            if (lane == 0) g_rowsum[r] = carry;
        }

        barrier_n(&g_sub_count, &g_sub_gen, NSUB);

        if (b < 8) {
            // ---- colpreT, coalesced via smem transpose tile ----
            int J = b * 32;
#pragma unroll
            for (int seg = 0; seg < 8; seg++) {
                int k = seg * 32 + w;
                int j = J + lane;
                float val = (j <= k) ? g_P[k * (k + 1) / 2 + j] : 0.f;
                sm.cp.tile[k * 33 + lane] = val;
            }
            __syncthreads();
            {
                float v[8];
#pragma unroll
                for (int seg = 0; seg < 8; seg++) v[seg] = sm.cp.tile[(seg * 32 + lane) * 33 + w];
                float carry = 0.f;
#pragma unroll
                for (int seg = 0; seg < 8; seg++) {
                    float x = v[seg];
#pragma unroll
                    for (int o = 1; o < 32; o <<= 1) { float u = __shfl_up_sync(0xffffffffu, x, o); if (lane >= o) x += u; }
                    x += carry;
                    v[seg] = x;
                    carry = __shfl_sync(0xffffffffu, x, 31);
                }
#pragma unroll
                for (int seg = 0; seg < 8; seg++) sm.cp.tile[(seg * 32 + lane) * 33 + w] = v[seg];
            }
            __syncthreads();
#pragma unroll
            for (int seg = 0; seg < 8; seg++) {
                int k = seg * 32 + w;
                g_colpreT[k * NMESH + J + lane] = sm.cp.tile[k * 33 + lane];
            }
        } else if (w == 0) {
            float v[8];
#pragma unroll
            for (int seg = 0; seg < 8; seg++) v[seg] = g_rowsum[seg * 32 + lane];
            float carry = 0.f;
#pragma unroll
            for (int seg = 0; seg < 8; seg++) {
                float x = v[seg];
#pragma unroll
                for (int o = 1; o < 32; o <<= 1) { float u = __shfl_up_sync(0xffffffffu, x, o); if (lane >= o) x += u; }
                x += carry;
                g_A[seg * 32 + lane + 1] = x;
                carry = __shfl_sync(0xffffffffu, x, 31);
            }
            if (lane == 0) g_A[0] = 0.f;
        }
    }

    barrier_n(&g_bar_count, &g_bar_gen, NWORK);

    // ================= Phase 3: chain walk (32 blocks, 128 outputs each) ===========
    int t = b * 128 + tid;
    bool active = (tid < 128);
    int T = t + 1;
    int st = active ? g_start[T] : 0;

    {
        const uint4* src = (const uint4*)g_il;
        uint4* dst = (uint4*)sm.walk.s_il;
        for (int i = tid; i < ILPAD / 4; i += TPB) dst[i] = src[i];
        for (int i = tid; i <= NMESH; i += TPB) sm.walk.s_A[i] = g_A[i];
    }
    __syncthreads();
    if (!active) return;

    int s = st >> 9;
    int Vmin = (st & 0x1FF) - 1;
    int lo = 0;
    float acc = 0.f;
    bool finished = false;

    while (!finished) {
        int hiA[CHUNK], VA[CHUNK], loA[CHUNK];
        bool act[CHUNK];
        bool done = false;
#pragma unroll
        for (int c = 0; c < CHUNK; c++) {
            act[c] = !done;
            if (!done) {
                int il = sm.walk.s_il[s];
                int hi = (unsigned)il >> 22;
                hiA[c] = hi; VA[c] = Vmin; loA[c] = lo;
                if (hi >= NMESH - 1) done = true;
                else {
                    Vmin = min(Vmin, (il & 0x1FF) - 1);
                    s = ((il >> 9) & 0x1FFF) - 1;
                    lo = hi;
                }
            } else { hiA[c] = 0; VA[c] = -1; loA[c] = 0; }
        }

        float a0 = 0.f, a1 = 0.f, a2 = 0.f, a3 = 0.f;
#pragma unroll
        for (int c = 0; c < CHUNK; c++) {
            float contrib = 0.f;
            if (act[c]) {
                int hi = hiA[c], V = VA[c], lol = loA[c];
                if (V >= hi - 1) {
                    contrib = sm.walk.s_A[hi] - sm.walk.s_A[lol];
                } else if (V >= 0) {
                    int m = max(lol, V + 1);
                    contrib = sm.walk.s_A[m] - sm.walk.s_A[lol]
                            + g_colpreT[(hi - 1) * NMESH + V]
                            - g_colpreT[(m - 1) * NMESH + V];
                }
            }
            if ((c & 3) == 0) a0 += contrib;
            else if ((c & 3) == 1) a1 += contrib;
            else if ((c & 3) == 2) a2 += contrib;
            else a3 += contrib;
        }
        acc += (a0 + a1) + (a2 + a3);
        finished = done;
    }

    float S = sm.walk.s_A[NMESH];
    out[t] = (2.f * acc - S) / S;
}

// ---------------- launch ----------------
extern "C" void kernel_launch(void* const* d_in, const int* in_sizes, int n_in,
                              void* d_out, int out_size) {
    const float* h   = nullptr;
    const float* raw = nullptr;
    const float* m2  = nullptr;
    const float* m3  = nullptr;
    for (int i = 0; i < n_in; i++) {
        if (in_sizes[i] == MSTEPS && !h)            h   = (const float*)d_in[i];
        else if (in_sizes[i] == TRI && !raw)        raw = (const float*)d_in[i];
        else if (in_sizes[i] == NMESH * NMESH) {
            if (!m2) m2 = (const float*)d_in[i];
            else     m3 = (const float*)d_in[i];
        }
    }
    if (!m3) m3 = m2;

    k_fused<<<NGRID, TPB>>>(h, raw, m2, m3, (float*)d_out);
}

// round 16
// speedup vs baseline: 1.1045x; 1.1045x over previous
#include <cuda_runtime.h>
#include <math.h>
#include <limits.h>

#define NMESH  256
#define MSTEPS 4096
#define SLEN   (MSTEPS + 1)     // scan steps 0..M (step 0 = pseudo init sweep-up at hc=1.0)
#define SLENP  4128             // padded to multiple of 32 (129 chunks)
#define NCH    (SLENP / 32)     // 129
#define NCHP   136
#define TRI    (NMESH * (NMESH + 1) / 2)
#define SENTD  32767
#define CHUNK  8
#define ILPAD  4112             // SLEN padded to multiple of 4 for uint4 copy
#define NWORK  32
#define NSUB   9                // density sub-barrier participants (blocks 0-8)
#define TPB    1024

// dynamic smem layout (bytes)
#define OFF_LIN    0            // float[256]            -> 1024
#define OFF_IU     1024         // short[SLENP]          -> 9280
#define OFF_D      9280         // short[SLENP]          -> 17536
#define OFF_LU     17536        // short[SLENP]          -> 25792
#define OFF_PM     25792        // short[SLENP]          -> 34048
#define OFF_SM     34048        // short[SLENP]          -> 42304
#define OFF_CMIN   42304        // short[NCHP]           -> 42576
#define OFF_CMAX   42576        // short[NCHP]           -> 42848
#define OFF_SC     42848        // int[32]               -> 42976
#define OFF_H_IL   42976        // float[4096] (phase1) / int[ILPAD] (walk) -> 59424
#define OFF_A      59424        // float[257]            -> 60452
#define DSM_BYTES  60480

// ---------------- device scratch ----------------
__device__ float  g_P[TRI];                   // per-row inclusive prefix of softplus density
__device__ float  g_rowsum[NMESH];
__device__ int    g_il[ILPAD];                // packed: (iu:9)<<22 | (link+1:13)<<9 | (segMin+1:9)
__device__ int    g_start[SLEN];              // packed: lastup<<9 | (dminLast+1)
__device__ float  g_A[NMESH + 1];             // prefix of rowsums; g_A[NMESH] = S
__device__ float  g_colpreT[NMESH * NMESH];   // colpreT[k*N+j] = sum_{r=j..k} P_r(j)

// barriers (generation-based; persist across graph replays)
__device__ volatile int g_bar_count = 0, g_bar_gen = 0;   // full (NWORK blocks)
__device__ volatile int g_sub_count = 0, g_sub_gen = 0;   // density group (NSUB blocks)

__device__ __forceinline__ void barrier_n(volatile int* cnt, volatile int* gen, int target) {
    __syncthreads();
    if (threadIdx.x == 0) {
        int g = *gen;
        __threadfence();
        if (atomicAdd((int*)cnt, 1) == target - 1) {
            *cnt = 0;
            __threadfence();
            *gen = g + 1;
        } else {
            while (*gen == g) { }
        }
        __threadfence();
    }
    __syncthreads();
}

__device__ __forceinline__ float softplusf(float x) {
    return fmaxf(x, 0.f) + log1pf(expf(-fabsf(x)));
}

// range-min of d over [l, r] using chunk tables (all smem, unrolled in-chunk)
__device__ __forceinline__ int rmin_d(const short* s_d, const short* pmind,
                                      const short* smind, const short* cmind,
                                      int l, int r) {
    int cl = l >> 5, cr = r >> 5;
    if (cl == cr) {
        int v = SENTD;
        int base = cl << 5;
#pragma unroll
        for (int ii = 0; ii < 32; ii++) {
            int idx = base + ii;
            int dv = s_d[idx];                    // independent LDS
            if (idx >= l && idx <= r) v = min(v, dv);
        }
        return v;
    }
    int v = min((int)smind[l], (int)pmind[r]);
    for (int cc = cl + 1; cc < cr; cc++) v = min(v, (int)cmind[cc]);
    return v;
}

__global__ void __launch_bounds__(TPB, 1) k_fused(const float* __restrict__ h,
                                                  const float* __restrict__ raw,
                                                  const float* __restrict__ m2,
                                                  const float* __restrict__ m3,
                                                  float* __restrict__ out) {
    extern __shared__ char dsm[];
    int b = blockIdx.x;
    int tid = threadIdx.x;
    int lane = tid & 31, w = tid >> 5;

    float* lin   = (float*)(dsm + OFF_LIN);
    short* s_iu  = (short*)(dsm + OFF_IU);
    short* s_d   = (short*)(dsm + OFF_D);
    short* s_lu  = (short*)(dsm + OFF_LU);
    short* pmind = (short*)(dsm + OFF_PM);
    short* smind = (short*)(dsm + OFF_SM);
    short* cmind = (short*)(dsm + OFF_CMIN);
    short* cmaxu = (short*)(dsm + OFF_CMAX);
    int*   sc    = (int*)(dsm + OFF_SC);
    float* s_h   = (float*)(dsm + OFF_H_IL);
    int*   s_il  = (int*)(dsm + OFF_H_IL);
    float* s_A   = (float*)(dsm + OFF_A);
    float* tile  = (float*)dsm;                 // density colpre overlay

    if (b >= 16) {
        // ============ meta pipeline (blocks 16-31, fully local) ============
        // stage h into smem (one coalesced round trip), plus lin
        {
            const uint4* src = (const uint4*)h;
            uint4* dst = (uint4*)s_h;
            if (tid < 1024) dst[tid] = src[tid];          // 4096 floats
        }
        if (tid < NMESH) {
            const float* xx = (m2[1] != m2[0]) ? m2 : m3;
            lin[tid] = xx[tid];
        }
        __syncthreads();

        // ---- classification: all-smem (arithmetic candidate + exact fixup) ----
        for (int s = tid; s < SLENP; s += TPB) {
            short iu = 0, dd = (short)SENTD;
            if (s < SLEN) {
                float hc, hp;
                if (s == 0) { hc = 1.0f; hp = s_h[MSTEPS - 1]; }
                else { hc = s_h[s - 1]; hp = (s == 1) ? 1.0f : s_h[s - 2]; }
                if (hc > hp) {
                    int m = (int)((hc + 1.0f) * 127.5f);
                    m = min(max(m, 0), 255);
                    while (m > 0 && lin[m - 1] >= hc) m--;
                    while (m < 256 && lin[m] < hc) m++;
                    iu = (short)m;
                } else if (hc < hp) {
                    int m = (int)((hc + 1.0f) * 127.5f);
                    m = min(max(m, 0), 255);
                    while (m > 0 && lin[m - 1] > hc) m--;
                    while (m < 256 && lin[m] <= hc) m++;
                    dd = (short)(m - 1);
                }
            }
            s_iu[s] = iu; s_d[s] = dd;
        }
        __syncthreads();

        // ---- lastup local + chunk mins fused ----
        int v_lu;
        int l0, l1, l2, l3;
        {
            int base = tid * 4;
            int w0 = (s_iu[base]     > 0) ? base     : -1;
            int w1 = (s_iu[base + 1] > 0) ? base + 1 : -1;
            int w2 = (s_iu[base + 2] > 0) ? base + 2 : -1;
            int w3 = (s_iu[base + 3] > 0) ? base + 3 : -1;
            l0 = w0; l1 = max(l0, w1); l2 = max(l1, w2); l3 = max(l2, w3);
            v_lu = l3;
#pragma unroll
            for (int o = 1; o < 32; o <<= 1) { int u = __shfl_up_sync(0xffffffffu, v_lu, o); if (lane >= o) v_lu = max(v_lu, u); }
            if (lane == 31) sc[w] = v_lu;
        }
        // chunk mins (independent of lastup scan)
        for (int c = w; c < NCH; c += 32) {
            int e = c * 32 + lane;
            int dv = s_d[e];
            int uv = s_iu[e];
            int p = dv;
#pragma unroll
            for (int o = 1; o < 32; o <<= 1) { int u = __shfl_up_sync(0xffffffffu, p, o); if (lane >= o) p = min(p, u); }
            pmind[e] = (short)p;
            int q = dv;
#pragma unroll
            for (int o = 1; o < 32; o <<= 1) { int u = __shfl_down_sync(0xffffffffu, q, o); if (lane + o < 32) q = min(q, u); }
            smind[e] = (short)q;
            if (lane == 31) cmind[c] = (short)p;
            int m = uv;
#pragma unroll
            for (int o = 16; o >= 1; o >>= 1) m = max(m, __shfl_xor_sync(0xffffffffu, m, o));
            if (lane == 0) cmaxu[c] = (short)m;
        }
        __syncthreads();
        if (w == 0) {
            int x = sc[lane];
#pragma unroll
            for (int o = 1; o < 32; o <<= 1) { int u = __shfl_up_sync(0xffffffffu, x, o); if (lane >= o) x = max(x, u); }
            sc[lane] = x;
        }
        __syncthreads();
        {
            int base = tid * 4;
            int warppre = (w > 0) ? sc[w - 1] : INT_MIN;
            int lanepre = __shfl_up_sync(0xffffffffu, v_lu, 1);
            int pre = (lane == 0) ? warppre : max(warppre, lanepre);
            s_lu[base]     = (short)max(pre, l0);
            s_lu[base + 1] = (short)max(pre, l1);
            s_lu[base + 2] = (short)max(pre, l2);
            s_lu[base + 3] = (short)max(pre, l3);
            if (tid == TPB - 1) {
                int w4 = (s_iu[4096] > 0) ? 4096 : -1;
                s_lu[4096] = (short)max(max(pre, l3), w4);
            }
        }
        __syncthreads();

        // ---- partB: each block handles 257 s-values from its local tables ----
        {
            int s = (b - 16) * 257 + tid;
            if (tid < 257 && s < SLEN) {
                int iu = s_iu[s];
                int lnk = -1;
                int e = 257;                              // segMin+1 encoding; 257 = +inf
                if (iu > 0 && iu < NMESH - 1) {
                    // PGE: rightmost s' < s with iu[s'] > iu (unrolled independent LDS)
                    int ci = (s - 1) >> 5;
                    int base = ci << 5;
                    int found = -1;
#pragma unroll
                    for (int ii = 0; ii < 32; ii++) {
                        int idx = base + ii;
                        int val = s_iu[idx];
                        if (idx < s && val > iu) found = idx;
                    }
                    if (found < 0) {
                        int c = ci - 1;
                        while ((int)cmaxu[c] <= iu) c--;
                        base = c << 5;
#pragma unroll
                        for (int ii = 0; ii < 32; ii++) {
                            int idx = base + ii;
                            int val = s_iu[idx];
                            if (val > iu) found = idx;
                        }
                    }
                    lnk = found;
                    int v = rmin_d(s_d, pmind, smind, cmind, lnk + 1, s);
                    e = min(v + 1, 257);
                }
                g_il[s] = (iu << 22) | ((lnk + 1) << 9) | e;

                // g_start: lastup + min d over (lastup, s]
                int lu = s_lu[s];
                int enc = 257;
                if (lu < s) {
                    int v = rmin_d(s_d, pmind, smind, cmind, lu + 1, s);
                    enc = min(v + 1, 257);
                }
                g_start[s] = (lu << 9) | enc;
            }
            if (b == 16 && tid >= 512 && tid < 512 + (ILPAD - SLEN)) g_il[SLEN + (tid - 512)] = 0;
        }
    } else if (b < NSUB) {
        // ============ density pipeline (blocks 0-8) ============
        if (b < 8) {
            int r = b * 32 + w;
            int off = r * (r + 1) / 2;
            float v[8];
#pragma unroll
            for (int seg = 0; seg < 8; seg++) {
                int idx = seg * 32 + lane;
                v[seg] = (idx <= r) ? raw[off + idx] : 0.f;
            }
#pragma unroll
            for (int seg = 0; seg < 8; seg++) {
                int idx = seg * 32 + lane;
                v[seg] = (idx <= r) ? softplusf(v[seg]) : 0.f;
            }
            float carry = 0.f;
#pragma unroll
            for (int seg = 0; seg < 8; seg++) {
                if (seg * 32 <= r) {
                    float x = v[seg];
#pragma unroll
                    for (int o = 1; o < 32; o <<= 1) { float u = __shfl_up_sync(0xffffffffu, x, o); if (lane >= o) x += u; }
                    x += carry;
                    int idx = seg * 32 + lane;
                    if (idx <= r) g_P[off + idx] = x;
                    carry = __shfl_sync(0xffffffffu, x, 31);
                }
            }
            if (lane == 0) g_rowsum[r] = carry;
        }

        barrier_n(&g_sub_count, &g_sub_gen, NSUB);

        if (b < 8) {
            // ---- colpreT, coalesced via smem transpose tile ----
            int J = b * 32;
#pragma unroll
            for (int seg = 0; seg < 8; seg++) {
                int k = seg * 32 + w;
                int j = J + lane;
                float val = (j <= k) ? g_P[k * (k + 1) / 2 + j] : 0.f;
                tile[k * 33 + lane] = val;
            }
            __syncthreads();
            {
                float v[8];
#pragma unroll
                for (int seg = 0; seg < 8; seg++) v[seg] = tile[(seg * 32 + lane) * 33 + w];
                float carry = 0.f;
#pragma unroll
                for (int seg = 0; seg < 8; seg++) {
                    float x = v[seg];
#pragma unroll
                    for (int o = 1; o < 32; o <<= 1) { float u = __shfl_up_sync(0xffffffffu, x, o); if (lane >= o) x += u; }
                    x += carry;
                    v[seg] = x;
                    carry = __shfl_sync(0xffffffffu, x, 31);
                }
#pragma unroll
                for (int seg = 0; seg < 8; seg++) tile[(seg * 32 + lane) * 33 + w] = v[seg];
            }
            __syncthreads();
#pragma unroll
            for (int seg = 0; seg < 8; seg++) {
                int k = seg * 32 + w;
                g_colpreT[k * NMESH + J + lane] = tile[k * 33 + lane];
            }
        } else if (w == 0) {
            // ---- block 8: A prefix of rowsums (one warp) ----
            float v[8];
#pragma unroll
            for (int seg = 0; seg < 8; seg++) v[seg] = g_rowsum[seg * 32 + lane];
            float carry = 0.f;
#pragma unroll
            for (int seg = 0; seg < 8; seg++) {
                float x = v[seg];
#pragma unroll
                for (int o = 1; o < 32; o <<= 1) { float u = __shfl_up_sync(0xffffffffu, x, o); if (lane >= o) x += u; }
                x += carry;
                g_A[seg * 32 + lane + 1] = x;
                carry = __shfl_sync(0xffffffffu, x, 31);
            }
            if (lane == 0) g_A[0] = 0.f;
        }
    }
    // blocks 9-15: straight to the full barrier

    barrier_n(&g_bar_count, &g_bar_gen, NWORK);

    // ================= Phase 3: chain walk (32 blocks, 128 outputs each) ===========
    int t = b * 128 + tid;
    bool active = (tid < 128);
    int T = t + 1;
    int st = active ? g_start[T] : 0;      // issue early

    {
        const uint4* src = (const uint4*)g_il;
        uint4* dst = (uint4*)s_il;
        for (int i = tid; i < ILPAD / 4; i += TPB) dst[i] = src[i];
        for (int i = tid; i <= NMESH; i += TPB) s_A[i] = g_A[i];
    }
    __syncthreads();
    if (!active) return;

    int s = st >> 9;
    int Vmin = (st & 0x1FF) - 1;    // 256 acts as +inf
    int lo = 0;
    float acc = 0.f;
    bool finished = false;

    while (!finished) {
        // ---- Phase A: LDS-only chase; record (lo, hi, V) per level ----
        int hiA[CHUNK], VA[CHUNK], loA[CHUNK];
        bool act[CHUNK];
        bool done = false;
#pragma unroll
        for (int c = 0; c < CHUNK; c++) {
            act[c] = !done;
            if (!done) {
                int il = s_il[s];
                int hi = (unsigned)il >> 22;
                hiA[c] = hi; VA[c] = Vmin; loA[c] = lo;
                if (hi >= NMESH - 1) done = true;
                else {
                    Vmin = min(Vmin, (il & 0x1FF) - 1);
                    s = ((il >> 9) & 0x1FFF) - 1;
                    lo = hi;
                }
            } else { hiA[c] = 0; VA[c] = -1; loA[c] = 0; }
        }

        // ---- Phase B: batched independent colpre/A accumulation ----
        float a0 = 0.f, a1 = 0.f, a2 = 0.f, a3 = 0.f;
#pragma unroll
        for (int c = 0; c < CHUNK; c++) {
            float contrib = 0.f;
            if (act[c]) {
                int hi = hiA[c], V = VA[c], lol = loA[c];
                if (V >= hi - 1) {
                    contrib = s_A[hi] - s_A[lol];
                } else if (V >= 0) {
                    int m = max(lol, V + 1);
                    contrib = s_A[m] - s_A[lol]
                            + g_colpreT[(hi - 1) * NMESH + V]
                            - g_colpreT[(m - 1) * NMESH + V];
                }
            }
            if ((c & 3) == 0) a0 += contrib;
            else if ((c & 3) == 1) a1 += contrib;
            else if ((c & 3) == 2) a2 += contrib;
            else a3 += contrib;
        }
        acc += (a0 + a1) + (a2 + a3);
        finished = done;
    }

    float S = s_A[NMESH];
    out[t] = (2.f * acc - S) / S;
}

// ---------------- launch: single fused kernel, dynamic smem ----------------
extern "C" void kernel_launch(void* const* d_in, const int* in_sizes, int n_in,
                              void* d_out, int out_size) {
    const float* h   = nullptr;
    const float* raw = nullptr;
    const float* m2  = nullptr;
    const float* m3  = nullptr;
    for (int i = 0; i < n_in; i++) {
        if (in_sizes[i] == MSTEPS && !h)            h   = (const float*)d_in[i];
        else if (in_sizes[i] == TRI && !raw)        raw = (const float*)d_in[i];
        else if (in_sizes[i] == NMESH * NMESH) {
            if (!m2) m2 = (const float*)d_in[i];
            else     m3 = (const float*)d_in[i];
        }
    }
    if (!m3) m3 = m2;

    static bool attr_done = false;
    if (!attr_done) {
        cudaFuncSetAttribute(k_fused, cudaFuncAttributeMaxDynamicSharedMemorySize, DSM_BYTES);
        attr_done = true;
    }

    k_fused<<<NWORK, TPB, DSM_BYTES>>>(h, raw, m2, m3, (float*)d_out);
}

// round 17
// speedup vs baseline: 1.1212x; 1.0152x over previous
#include <cuda_runtime.h>
#include <math.h>
#include <limits.h>

#define NMESH  256
#define MSTEPS 4096
#define SLEN   (MSTEPS + 1)     // scan steps 0..M (step 0 = pseudo init sweep-up at hc=1.0)
#define SLENP  4128             // padded to multiple of 32 (129 chunks)
#define NCH    (SLENP / 32)     // 129
#define NCHP   136
#define TRI    (NMESH * (NMESH + 1) / 2)
#define SENTD  32767
#define CHUNK  8
#define ILPAD  4112             // SLEN padded to multiple of 4 for uint4 copy
#define NWORK  32
#define NSUB   9                // density sub-barrier participants (blocks 0-8)
#define TPB    1024

// ---------------- device scratch ----------------
__device__ float  g_P[TRI];                   // per-row inclusive prefix of softplus density
__device__ float  g_rowsum[NMESH];
__device__ int    g_il[ILPAD];                // packed: (iu:9)<<22 | (link+1:13)<<9 | (segMin+1:9)
__device__ int    g_start[SLEN];              // packed: lastup<<9 | (dminLast+1)
__device__ float  g_A[NMESH + 1];             // prefix of rowsums; g_A[NMESH] = S
__device__ float  g_colpreT[NMESH * NMESH];   // colpreT[k*N+j] = sum_{r=j..k} P_r(j)

// sub-barrier (generation-based; persists across graph replays)
__device__ volatile int g_sub_count = 0, g_sub_gen = 0;   // density group (NSUB blocks)

__device__ __forceinline__ void barrier_n(volatile int* cnt, volatile int* gen, int target) {
    __syncthreads();
    if (threadIdx.x == 0) {
        int g = *gen;
        __threadfence();
        if (atomicAdd((int*)cnt, 1) == target - 1) {
            *cnt = 0;
            __threadfence();
            *gen = g + 1;
        } else {
            while (*gen == g) { }
        }
        __threadfence();
    }
    __syncthreads();
}

__device__ __forceinline__ float softplusf(float x) {
    return fmaxf(x, 0.f) + log1pf(expf(-fabsf(x)));
}

// shared-memory overlay for k_pre
union SMemPre {
    struct {   // meta pipeline, blocks 16-31 (redundant metaA + local partB)
        float lin[NMESH];
        short s_iu[SLENP];
        short s_d[SLENP];
        short s_lu[SLENP];
        short pmind[SLENP];
        short smind[SLENP];
        short cmind[NCHP];
        short cmaxu[NCHP];
        int   sc[32];
    } meta;
    struct {   // colpre tile, blocks 0-7
        float tile[NMESH * 33];   // padded stride 33 -> conflict-free column access
    } cp;
};

// range-min of d over [l, r] using chunk tables (all smem, unrolled in-chunk)
__device__ __forceinline__ int rmin_d(const short* s_d, const short* pmind,
                                      const short* smind, const short* cmind,
                                      int l, int r) {
    int cl = l >> 5, cr = r >> 5;
    if (cl == cr) {
        int v = SENTD;
        int base = cl << 5;
#pragma unroll
        for (int ii = 0; ii < 32; ii++) {
            int idx = base + ii;
            int dv = s_d[idx];                    // independent LDS
            if (idx >= l && idx <= r) v = min(v, dv);
        }
        return v;
    }
    int v = min((int)smind[l], (int)pmind[r]);
    for (int cc = cl + 1; cc < cr; cc++) v = min(v, (int)cmind[cc]);
    return v;
}

// =================== kernel A: density + meta pipelines ===================
__global__ void __launch_bounds__(TPB, 1) k_pre(const float* __restrict__ h,
                                                const float* __restrict__ raw,
                                                const float* __restrict__ m2,
                                                const float* __restrict__ m3) {
    __shared__ SMemPre sm;
    int b = blockIdx.x;
    int tid = threadIdx.x;
    int lane = tid & 31, w = tid >> 5;

    if (b >= 16) {
        // ============ meta pipeline (blocks 16-31, fully local) ============
        if (tid < NMESH) {
            const float* xx = (m2[1] != m2[0]) ? m2 : m3;
            sm.meta.lin[tid] = xx[tid];
        }
        __syncthreads();

        // ---- classification: arithmetic candidate + exact fixup on mesh floats ----
        for (int s = tid; s < SLENP; s += TPB) {
            short iu = 0, dd = (short)SENTD;
            if (s < SLEN) {
                float hc, hp;
                if (s == 0) { hc = 1.0f; hp = h[MSTEPS - 1]; }
                else { hc = h[s - 1]; hp = (s == 1) ? 1.0f : h[s - 2]; }
                if (hc > hp) {
                    int m = (int)((hc + 1.0f) * 127.5f);
                    m = min(max(m, 0), 255);
                    while (m > 0 && sm.meta.lin[m - 1] >= hc) m--;
                    while (m < 256 && sm.meta.lin[m] < hc) m++;
                    iu = (short)m;
                } else if (hc < hp) {
                    int m = (int)((hc + 1.0f) * 127.5f);
                    m = min(max(m, 0), 255);
                    while (m > 0 && sm.meta.lin[m - 1] > hc) m--;
                    while (m < 256 && sm.meta.lin[m] <= hc) m++;
                    dd = (short)(m - 1);
                }
            }
            sm.meta.s_iu[s] = iu; sm.meta.s_d[s] = dd;
        }
        __syncthreads();

        // ---- lastup local + chunk mins fused (one barrier serves both) ----
        int v_lu;
        int l0, l1, l2, l3;
        {
            int base = tid * 4;
            int w0 = (sm.meta.s_iu[base]     > 0) ? base     : -1;
            int w1 = (sm.meta.s_iu[base + 1] > 0) ? base + 1 : -1;
            int w2 = (sm.meta.s_iu[base + 2] > 0) ? base + 2 : -1;
            int w3 = (sm.meta.s_iu[base + 3] > 0) ? base + 3 : -1;
            l0 = w0; l1 = max(l0, w1); l2 = max(l1, w2); l3 = max(l2, w3);
            v_lu = l3;
#pragma unroll
            for (int o = 1; o < 32; o <<= 1) { int u = __shfl_up_sync(0xffffffffu, v_lu, o); if (lane >= o) v_lu = max(v_lu, u); }
            if (lane == 31) sm.meta.sc[w] = v_lu;
        }
        // chunk mins (independent of lastup scan; reads s_iu/s_d only)
        for (int c = w; c < NCH; c += 32) {
            int e = c * 32 + lane;
            int dv = sm.meta.s_d[e];
            int uv = sm.meta.s_iu[e];
            int p = dv;
#pragma unroll
            for (int o = 1; o < 32; o <<= 1) { int u = __shfl_up_sync(0xffffffffu, p, o); if (lane >= o) p = min(p, u); }
            sm.meta.pmind[e] = (short)p;
            int q = dv;
#pragma unroll
            for (int o = 1; o < 32; o <<= 1) { int u = __shfl_down_sync(0xffffffffu, q, o); if (lane + o < 32) q = min(q, u); }
            sm.meta.smind[e] = (short)q;
            if (lane == 31) sm.meta.cmind[c] = (short)p;
            int m = uv;
#pragma unroll
            for (int o = 16; o >= 1; o >>= 1) m = max(m, __shfl_xor_sync(0xffffffffu, m, o));
            if (lane == 0) sm.meta.cmaxu[c] = (short)m;
        }
        __syncthreads();
        if (w == 0) {
            int x = sm.meta.sc[lane];
#pragma unroll
            for (int o = 1; o < 32; o <<= 1) { int u = __shfl_up_sync(0xffffffffu, x, o); if (lane >= o) x = max(x, u); }
            sm.meta.sc[lane] = x;
        }
        __syncthreads();
        {
            int base = tid * 4;
            int warppre = (w > 0) ? sm.meta.sc[w - 1] : INT_MIN;
            int lanepre = __shfl_up_sync(0xffffffffu, v_lu, 1);
            int pre = (lane == 0) ? warppre : max(warppre, lanepre);
            sm.meta.s_lu[base]     = (short)max(pre, l0);
            sm.meta.s_lu[base + 1] = (short)max(pre, l1);
            sm.meta.s_lu[base + 2] = (short)max(pre, l2);
            sm.meta.s_lu[base + 3] = (short)max(pre, l3);
            if (tid == TPB - 1) {
                int w4 = (sm.meta.s_iu[4096] > 0) ? 4096 : -1;
                sm.meta.s_lu[4096] = (short)max(max(pre, l3), w4);
            }
        }
        __syncthreads();

        // ---- partB: each block handles 257 s-values from its local tables ----
        {
            int s = (b - 16) * 257 + tid;
            if (tid < 257 && s < SLEN) {
                int iu = sm.meta.s_iu[s];
                int lnk = -1;
                int e = 257;                              // segMin+1 encoding; 257 = +inf
                if (iu > 0 && iu < NMESH - 1) {
                    // PGE: rightmost s' < s with iu[s'] > iu (unrolled independent LDS)
                    int ci = (s - 1) >> 5;
                    int base = ci << 5;
                    int found = -1;
#pragma unroll
                    for (int ii = 0; ii < 32; ii++) {
                        int idx = base + ii;
                        int val = sm.meta.s_iu[idx];
                        if (idx < s && val > iu) found = idx;
                    }
                    if (found < 0) {
                        int c = ci - 1;
                        while ((int)sm.meta.cmaxu[c] <= iu) c--;
                        base = c << 5;
#pragma unroll
                        for (int ii = 0; ii < 32; ii++) {
                            int idx = base + ii;
                            int val = sm.meta.s_iu[idx];
                            if (val > iu) found = idx;
                        }
                    }
                    lnk = found;
                    int v = rmin_d(sm.meta.s_d, sm.meta.pmind, sm.meta.smind, sm.meta.cmind, lnk + 1, s);
                    e = min(v + 1, 257);
                }
                g_il[s] = (iu << 22) | ((lnk + 1) << 9) | e;

                // g_start: lastup + min d over (lastup, s]
                int lu = sm.meta.s_lu[s];
                int enc = 257;
                if (lu < s) {
                    int v = rmin_d(sm.meta.s_d, sm.meta.pmind, sm.meta.smind, sm.meta.cmind, lu + 1, s);
                    enc = min(v + 1, 257);
                }
                g_start[s] = (lu << 9) | enc;
            }
            if (b == 16 && tid >= 512 && tid < 512 + (ILPAD - SLEN)) g_il[SLEN + (tid - 512)] = 0;
        }
    } else if (b < NSUB) {
        // ============ density pipeline (blocks 0-8) ============
        if (b < 8) {
            int r = b * 32 + w;
            int off = r * (r + 1) / 2;
            float v[8];
#pragma unroll
            for (int seg = 0; seg < 8; seg++) {
                int idx = seg * 32 + lane;
                v[seg] = (idx <= r) ? raw[off + idx] : 0.f;   // independent loads
            }
#pragma unroll
            for (int seg = 0; seg < 8; seg++) {
                int idx = seg * 32 + lane;
                v[seg] = (idx <= r) ? softplusf(v[seg]) : 0.f;
            }
            float carry = 0.f;
#pragma unroll
            for (int seg = 0; seg < 8; seg++) {
                if (seg * 32 <= r) {       // warp-uniform
                    float x = v[seg];
#pragma unroll
                    for (int o = 1; o < 32; o <<= 1) { float u = __shfl_up_sync(0xffffffffu, x, o); if (lane >= o) x += u; }
                    x += carry;
                    int idx = seg * 32 + lane;
                    if (idx <= r) g_P[off + idx] = x;
                    carry = __shfl_sync(0xffffffffu, x, 31);
                }
            }
            if (lane == 0) g_rowsum[r] = carry;
        }

        barrier_n(&g_sub_count, &g_sub_gen, NSUB);   // rowprefix -> colpre (blocks 0-8)

        if (b < 8) {
            // ---- colpreT, fully coalesced via smem transpose tile ----
            int J = b * 32;
#pragma unroll
            for (int seg = 0; seg < 8; seg++) {
                int k = seg * 32 + w;
                int j = J + lane;
                float val = (j <= k) ? g_P[k * (k + 1) / 2 + j] : 0.f;
                sm.cp.tile[k * 33 + lane] = val;
            }
            __syncthreads();
            {
                float v[8];
#pragma unroll
                for (int seg = 0; seg < 8; seg++) v[seg] = sm.cp.tile[(seg * 32 + lane) * 33 + w];
                float carry = 0.f;
#pragma unroll
                for (int seg = 0; seg < 8; seg++) {
                    float x = v[seg];
#pragma unroll
                    for (int o = 1; o < 32; o <<= 1) { float u = __shfl_up_sync(0xffffffffu, x, o); if (lane >= o) x += u; }
                    x += carry;
                    v[seg] = x;
                    carry = __shfl_sync(0xffffffffu, x, 31);
                }
#pragma unroll
                for (int seg = 0; seg < 8; seg++) sm.cp.tile[(seg * 32 + lane) * 33 + w] = v[seg];
            }
            __syncthreads();
#pragma unroll
            for (int seg = 0; seg < 8; seg++) {
                int k = seg * 32 + w;
                g_colpreT[k * NMESH + J + lane] = sm.cp.tile[k * 33 + lane];
            }
        } else if (w == 0) {
            // ---- block 8: A prefix of rowsums (one warp) ----
            float v[8];
#pragma unroll
            for (int seg = 0; seg < 8; seg++) v[seg] = g_rowsum[seg * 32 + lane];
            float carry = 0.f;
#pragma unroll
            for (int seg = 0; seg < 8; seg++) {
                float x = v[seg];
#pragma unroll
                for (int o = 1; o < 32; o <<= 1) { float u = __shfl_up_sync(0xffffffffu, x, o); if (lane >= o) x += u; }
                x += carry;
                g_A[seg * 32 + lane + 1] = x;
                carry = __shfl_sync(0xffffffffu, x, 31);
            }
            if (lane == 0) g_A[0] = 0.f;
        }
    }
    // blocks 9-15: nothing
}

// =================== kernel B: chain walk ===================
__global__ void __launch_bounds__(TPB, 1) k_walk(float* __restrict__ out) {
    __shared__ int   s_il[ILPAD];
    __shared__ float s_A[NMESH + 1];
    int b = blockIdx.x;
    int tid = threadIdx.x;

    int t = b * 128 + tid;                 // 32*128 = 4096 outputs
    bool active = (tid < 128);
    int T = t + 1;
    int st = active ? g_start[T] : 0;      // issue early

    {
        const uint4* src = (const uint4*)g_il;
        uint4* dst = (uint4*)s_il;
        for (int i = tid; i < ILPAD / 4; i += TPB) dst[i] = src[i];
        for (int i = tid; i <= NMESH; i += TPB) s_A[i] = g_A[i];
    }
    __syncthreads();
    if (!active) return;

    int s = st >> 9;
    int Vmin = (st & 0x1FF) - 1;    // 256 acts as +inf
    int lo = 0;
    float acc = 0.f;
    bool finished = false;

    while (!finished) {
        // ---- Phase A: LDS-only chase; record (lo, hi, V) per level ----
        int hiA[CHUNK], VA[CHUNK], loA[CHUNK];
        bool act[CHUNK];
        bool done = false;
#pragma unroll
        for (int c = 0; c < CHUNK; c++) {
            act[c] = !done;
            if (!done) {
                int il = s_il[s];
                int hi = (unsigned)il >> 22;
                hiA[c] = hi; VA[c] = Vmin; loA[c] = lo;
                if (hi >= NMESH - 1) done = true;
                else {
                    Vmin = min(Vmin, (il & 0x1FF) - 1);
                    s = ((il >> 9) & 0x1FFF) - 1;
                    lo = hi;
                }
            } else { hiA[c] = 0; VA[c] = -1; loA[c] = 0; }
        }

        // ---- Phase B: batched independent colpre/A accumulation ----
        float a0 = 0.f, a1 = 0.f, a2 = 0.f, a3 = 0.f;
#pragma unroll
        for (int c = 0; c < CHUNK; c++) {
            float contrib = 0.f;
            if (act[c]) {
                int hi = hiA[c], V = VA[c], lol = loA[c];
                if (V >= hi - 1) {
                    contrib = s_A[hi] - s_A[lol];
                } else if (V >= 0) {
                    int m = max(lol, V + 1);
                    contrib = s_A[m] - s_A[lol]
                            + g_colpreT[(hi - 1) * NMESH + V]
                            - g_colpreT[(m - 1) * NMESH + V];
                }
            }
            if ((c & 3) == 0) a0 += contrib;
            else if ((c & 3) == 1) a1 += contrib;
            else if ((c & 3) == 2) a2 += contrib;
            else a3 += contrib;
        }
        acc += (a0 + a1) + (a2 + a3);
        finished = done;
    }

    float S = s_A[NMESH];
    out[t] = (2.f * acc - S) / S;
}

// ---------------- launch: two kernels (phase attribution via ncu) ----------------
extern "C" void kernel_launch(void* const* d_in, const int* in_sizes, int n_in,
                              void* d_out, int out_size) {
    const float* h   = nullptr;
    const float* raw = nullptr;
    const float* m2  = nullptr;
    const float* m3  = nullptr;
    for (int i = 0; i < n_in; i++) {
        if (in_sizes[i] == MSTEPS && !h)            h   = (const float*)d_in[i];
        else if (in_sizes[i] == TRI && !raw)        raw = (const float*)d_in[i];
        else if (in_sizes[i] == NMESH * NMESH) {
            if (!m2) m2 = (const float*)d_in[i];
            else     m3 = (const float*)d_in[i];
        }
    }
    if (!m3) m3 = m2;

    k_pre<<<NWORK, TPB>>>(h, raw, m2, m3);
    k_walk<<<NWORK, TPB>>>((float*)d_out);
}